// round 2
// baseline (speedup 1.0000x reference)
#include <cuda_runtime.h>

#define NROW 4096
#define DDIM 512

// Scratch (allocation-free rule: __device__ globals)
__device__ float g_sq[NROW];
__device__ float g_rowmax[NROW];   // max_distance per row (idempotent atomicMax)
__device__ float g_posmax[NROW];   // hardest positive per row (idempotent atomicMax)
__device__ float g_pen[NROW];      // relu(margin - hardest_negative)
__device__ float g_dist[(size_t)NROW * NROW];  // 64 MB dist matrix

// ---------------------------------------------------------------------------
// Kernel 1: squared norms
// ---------------------------------------------------------------------------
__global__ void sq_kernel(const float* __restrict__ X) {
    int row = blockIdx.x;
    const float4* xr = reinterpret_cast<const float4*>(X + (size_t)row * DDIM);
    float s = 0.f;
    for (int t = threadIdx.x; t < DDIM / 4; t += blockDim.x) {
        float4 v = xr[t];
        s += v.x * v.x + v.y * v.y + v.z * v.z + v.w * v.w;
    }
    #pragma unroll
    for (int o = 16; o > 0; o >>= 1) s += __shfl_xor_sync(0xffffffffu, s, o);
    __shared__ float ws[4];
    if ((threadIdx.x & 31) == 0) ws[threadIdx.x >> 5] = s;
    __syncthreads();
    if (threadIdx.x == 0) g_sq[row] = ws[0] + ws[1] + ws[2] + ws[3];
}

// ---------------------------------------------------------------------------
// Kernel 2: fused GEMM (X @ X^T) -> dist, row max, masked positive max
//   128x128 tile, BK=8, 256 threads, 8x8 per-thread register tile
// ---------------------------------------------------------------------------
__global__ __launch_bounds__(256, 2) void dist_kernel(const float* __restrict__ X,
                                                      const int* __restrict__ lab) {
    constexpr int BM = 128, BN = 128, BK = 8;
    __shared__ float As[BK][BM + 4];
    __shared__ float Bs[BK][BN + 4];
    __shared__ int smax[BM];
    __shared__ int spos[BM];

    const int m0 = blockIdx.y * BM;
    const int n0 = blockIdx.x * BN;
    const int tid = (int)threadIdx.x;
    const int tx = tid & 15;        // 16 cols of threads
    const int ty = tid >> 4;        // 16 rows of threads
    const int lrow = tid >> 1;      // 0..127 (tile row loaded)
    const int lcol = (tid & 1) * 4; // 0 or 4 (k offset loaded, float4)

    const float* Aptr = X + (size_t)(m0 + lrow) * DDIM + lcol;
    const float* Bptr = X + (size_t)(n0 + lrow) * DDIM + lcol;

    float acc[8][8];
    #pragma unroll
    for (int r = 0; r < 8; r++)
        #pragma unroll
        for (int s = 0; s < 8; s++) acc[r][s] = 0.f;

    for (int k0 = 0; k0 < DDIM; k0 += BK) {
        float4 a = *reinterpret_cast<const float4*>(Aptr + k0);
        float4 b = *reinterpret_cast<const float4*>(Bptr + k0);
        As[lcol + 0][lrow] = a.x; As[lcol + 1][lrow] = a.y;
        As[lcol + 2][lrow] = a.z; As[lcol + 3][lrow] = a.w;
        Bs[lcol + 0][lrow] = b.x; Bs[lcol + 1][lrow] = b.y;
        Bs[lcol + 2][lrow] = b.z; Bs[lcol + 3][lrow] = b.w;
        __syncthreads();
        #pragma unroll
        for (int kk = 0; kk < BK; kk++) {
            float4 a0 = *reinterpret_cast<const float4*>(&As[kk][ty * 8]);
            float4 a1 = *reinterpret_cast<const float4*>(&As[kk][ty * 8 + 4]);
            float4 b0 = *reinterpret_cast<const float4*>(&Bs[kk][tx * 8]);
            float4 b1 = *reinterpret_cast<const float4*>(&Bs[kk][tx * 8 + 4]);
            float av[8] = {a0.x, a0.y, a0.z, a0.w, a1.x, a1.y, a1.z, a1.w};
            float bv[8] = {b0.x, b0.y, b0.z, b0.w, b1.x, b1.y, b1.z, b1.w};
            #pragma unroll
            for (int r = 0; r < 8; r++)
                #pragma unroll
                for (int s = 0; s < 8; s++)
                    acc[r][s] = fmaf(av[r], bv[s], acc[r][s]);
        }
        __syncthreads();
    }

    if (tid < BM) { smax[tid] = 0; spos[tid] = 0; }
    __syncthreads();

    float sqn[8];
    int ln[8];
    #pragma unroll
    for (int s = 0; s < 8; s++) {
        int j = n0 + tx * 8 + s;
        sqn[s] = g_sq[j];
        ln[s] = lab[j];
    }

    #pragma unroll
    for (int r = 0; r < 8; r++) {
        int i = m0 + ty * 8 + r;
        float sqi = g_sq[i];
        int li = lab[i];
        float rmax = 0.f, pmax = 0.f;
        float dv[8];
        #pragma unroll
        for (int s = 0; s < 8; s++) {
            int j = n0 + tx * 8 + s;
            float d2 = sqi + sqn[s] - 2.f * acc[r][s];
            float d = sqrtf(fmaxf(d2, 0.f) + 1e-12f);
            dv[s] = d;
            rmax = fmaxf(rmax, d);
            if (li == ln[s] && i != j) pmax = fmaxf(pmax, d);
        }
        float4* dst = reinterpret_cast<float4*>(&g_dist[(size_t)i * NROW + n0 + tx * 8]);
        dst[0] = make_float4(dv[0], dv[1], dv[2], dv[3]);
        dst[1] = make_float4(dv[4], dv[5], dv[6], dv[7]);
        // dist >= 0 so int-compare == float-compare
        atomicMax(&smax[ty * 8 + r], __float_as_int(rmax));
        atomicMax(&spos[ty * 8 + r], __float_as_int(pmax));
    }
    __syncthreads();
    if (tid < BM) {
        atomicMax(reinterpret_cast<int*>(&g_rowmax[m0 + tid]), smax[tid]);
        atomicMax(reinterpret_cast<int*>(&g_posmax[m0 + tid]), spos[tid]);
    }
}

// ---------------------------------------------------------------------------
// Kernel 3: hardest negative per row.
//   negative_distance[i][j] = dist[i][j] + max_distance[j] * not_negative[i][j]
//   (reference broadcasts max_distance along the LAST dim -> index j)
// ---------------------------------------------------------------------------
__global__ void hneg_kernel(const int* __restrict__ lab) {
    const int i = blockIdx.x;
    const int li = lab[i];
    const float* drow = g_dist + (size_t)i * NROW;
    float mn = 3.4028235e38f;
    for (int j = threadIdx.x; j < NROW; j += blockDim.x) {
        float v = drow[j];
        if (lab[j] == li || j == i) v += g_rowmax[j];
        mn = fminf(mn, v);
    }
    #pragma unroll
    for (int o = 16; o > 0; o >>= 1) mn = fminf(mn, __shfl_xor_sync(0xffffffffu, mn, o));
    __shared__ float ws[8];
    if ((threadIdx.x & 31) == 0) ws[threadIdx.x >> 5] = mn;
    __syncthreads();
    if (threadIdx.x == 0) {
        float m = ws[0];
        #pragma unroll
        for (int w = 1; w < 8; w++) m = fminf(m, ws[w]);
        g_pen[i] = fmaxf(0.5f - m, 0.f);   // relu(MARGIN - hardest_negative)
    }
}

// ---------------------------------------------------------------------------
// Kernel 4: final deterministic reduction -> scalar loss
// ---------------------------------------------------------------------------
__global__ void final_kernel(float* __restrict__ out) {
    float s = 0.f;
    for (int i = threadIdx.x; i < NROW; i += blockDim.x)
        s += g_posmax[i] + g_pen[i];
    #pragma unroll
    for (int o = 16; o > 0; o >>= 1) s += __shfl_xor_sync(0xffffffffu, s, o);
    __shared__ float ws[32];
    if ((threadIdx.x & 31) == 0) ws[threadIdx.x >> 5] = s;
    __syncthreads();
    if (threadIdx.x == 0) {
        float t = 0.f;
        #pragma unroll
        for (int w = 0; w < 32; w++) t += ws[w];
        out[0] = t / (float)NROW;
    }
}

// ---------------------------------------------------------------------------
extern "C" void kernel_launch(void* const* d_in, const int* in_sizes, int n_in,
                              void* d_out, int out_size) {
    const float* X = (const float*)d_in[0];
    const int* lab = (const int*)d_in[1];
    float* out = (float*)d_out;

    sq_kernel<<<NROW, 128>>>(X);
    dist_kernel<<<dim3(NROW / 128, NROW / 128), 256>>>(X, lab);
    hneg_kernel<<<NROW, 256>>>(lab);
    final_kernel<<<1, 1024>>>(out);
}

// round 4
// speedup vs baseline: 4.2208x; 4.2208x over previous
#include <cuda_runtime.h>
#include <cstdint>

#define NROW 4096
#define DDIM 512

// -------------------------- device scratch (no allocs) ----------------------
__device__ float g_sq[NROW];
__device__ float g_rowmax[NROW];   // max_distance per row (idempotent atomicMax)
__device__ float g_posmax[NROW];   // hardest positive per row
__device__ float g_pen[NROW];      // relu(margin - hardest_negative)
__device__ float g_dist[(size_t)NROW * NROW];      // 64 MB dist matrix
__device__ uint32_t g_tf[(size_t)NROW * DDIM];     // tf32-rounded features

// -------------------------- PTX helpers -------------------------------------
__device__ __forceinline__ uint32_t smem_u32(const void* p) {
    uint32_t a;
    asm("{ .reg .u64 t; cvta.to.shared.u64 t, %1; cvt.u32.u64 %0, t; }" : "=r"(a) : "l"(p));
    return a;
}

#define CP_ASYNC16(dst, src) \
    asm volatile("cp.async.cg.shared.global [%0], [%1], 16;" :: "r"(dst), "l"(src) : "memory")
#define CP_COMMIT() asm volatile("cp.async.commit_group;" ::: "memory")
#define CP_WAIT(n)  asm volatile("cp.async.wait_group %0;" :: "n"(n) : "memory")

// D(16x8) += A(16x8, row-major) * B(8x8, col-major i.e. B[n][k])
__device__ __forceinline__ void mma_tf32(float* d, const uint32_t* a, uint32_t b0, uint32_t b1) {
    asm volatile(
        "mma.sync.aligned.m16n8k8.row.col.f32.tf32.tf32.f32 "
        "{%0,%1,%2,%3}, {%4,%5,%6,%7}, {%8,%9}, {%0,%1,%2,%3};"
        : "+f"(d[0]), "+f"(d[1]), "+f"(d[2]), "+f"(d[3])
        : "r"(a[0]), "r"(a[1]), "r"(a[2]), "r"(a[3]), "r"(b0), "r"(b1));
}

// -------------------------- SMEM layout (dynamic) ---------------------------
// [0]    s_sqi[128]  [512] s_sqj[128]  [1024] s_labi[128]  [1536] s_labj[128]
// [2048] 2 stages x (A[128][36] + B[128][36]) fp32  (36864 B per stage)
//        epilogue reuses [2048] as sd[128][129] fp32 (66048 B)
#define SM_SQI   0
#define SM_SQJ   512
#define SM_LABI  1024
#define SM_LABJ  1536
#define SM_BUF   2048
#define STAGE_BYTES 36864          // 2 * 128*36*4
#define TILE_STRIDE 36             // floats per row (32 + 4 pad)
#define SMEM_TOTAL (SM_BUF + 2 * STAGE_BYTES)

// ---------------------------------------------------------------------------
// Kernel 0: tf32 rounding + squared norms (one block per row, 128 threads)
// ---------------------------------------------------------------------------
__global__ void conv_kernel(const float* __restrict__ X) {
    int row = blockIdx.x;
    const float4* xr = reinterpret_cast<const float4*>(X + (size_t)row * DDIM);
    uint32_t* tf = g_tf + (size_t)row * DDIM;
    int t = threadIdx.x;           // 0..127, one float4 each
    float4 v = xr[t];
    float vv[4] = {v.x, v.y, v.z, v.w};
    float s = 0.f;
    uint32_t o[4];
    #pragma unroll
    for (int k = 0; k < 4; k++) {
        float x = vv[k];
        s += x * x;
        asm("cvt.rna.tf32.f32 %0, %1;" : "=r"(o[k]) : "f"(x));
    }
    *reinterpret_cast<uint4*>(tf + t * 4) = make_uint4(o[0], o[1], o[2], o[3]);
    #pragma unroll
    for (int q = 16; q > 0; q >>= 1) s += __shfl_xor_sync(0xffffffffu, s, q);
    __shared__ float ws[4];
    if ((t & 31) == 0) ws[t >> 5] = s;
    __syncthreads();
    if (t == 0) g_sq[row] = ws[0] + ws[1] + ws[2] + ws[3];
}

// ---------------------------------------------------------------------------
// Kernel 1: tf32 mma.sync Gram + distance epilogue (upper-triangular tiles)
// ---------------------------------------------------------------------------
__device__ __forceinline__ void load_chunk(uint32_t stage_base, int m0, int n0, int k0, int tid) {
    #pragma unroll
    for (int t = 0; t < 2; t++) {        // 0 = A rows, 1 = B rows
        int r0 = t ? n0 : m0;
        uint32_t dbase = stage_base + t * (STAGE_BYTES / 2);
        #pragma unroll
        for (int q = 0; q < 4; q++) {
            int idx = q * 256 + tid;     // 0..1023
            int row = idx >> 3;
            int seg = idx & 7;           // 8 x 16B = 32 floats per row
            const uint32_t* gs = g_tf + (size_t)(r0 + row) * DDIM + k0 + seg * 4;
            CP_ASYNC16(dbase + (uint32_t)(row * (TILE_STRIDE * 4) + seg * 16), gs);
        }
    }
    CP_COMMIT();
}

__global__ __launch_bounds__(256, 2) void dist_kernel(const int* __restrict__ lab) {
    const int bi = blockIdx.y, bj = blockIdx.x;
    if (bj < bi) return;                 // symmetric: upper triangle only
    const int m0 = bi * 128, n0 = bj * 128;
    const bool diag = (bi == bj);

    extern __shared__ char smem[];
    const uint32_t sb = smem_u32(smem);
    const int tid = (int)threadIdx.x;
    const int wid = tid >> 5, lane = tid & 31;
    const int grp = lane >> 2, tig = lane & 3;     // groupID / threadIDInGroup
    const int mOff = (wid >> 1) * 32;              // warp tile: 32 x 64
    const int nOff = (wid & 1) * 64;

    if (tid < 128) {
        *(float*)(smem + SM_SQI + tid * 4) = g_sq[m0 + tid];
        *(int*)(smem + SM_LABI + tid * 4) = lab[m0 + tid];
    } else {
        int q = tid - 128;
        *(float*)(smem + SM_SQJ + q * 4) = g_sq[n0 + q];
        *(int*)(smem + SM_LABJ + q * 4) = lab[n0 + q];
    }

    float acc[2][8][4];
    #pragma unroll
    for (int mt = 0; mt < 2; mt++)
        #pragma unroll
        for (int nt = 0; nt < 8; nt++)
            #pragma unroll
            for (int e = 0; e < 4; e++) acc[mt][nt][e] = 0.f;

    // 2-stage cp.async pipeline over 16 K-chunks of 32
    load_chunk(sb + SM_BUF, m0, n0, 0, tid);
    #pragma unroll 1
    for (int c = 0; c < 16; c++) {
        if (c + 1 < 16) {
            load_chunk(sb + SM_BUF + ((c + 1) & 1) * STAGE_BYTES, m0, n0, (c + 1) * 32, tid);
            CP_WAIT(1);
        } else {
            CP_WAIT(0);
        }
        __syncthreads();     // chunk c visible to all
        const uint32_t* As = (const uint32_t*)(smem + SM_BUF + (c & 1) * STAGE_BYTES);
        const uint32_t* Bs = As + (STAGE_BYTES / 8);   // /2 bytes -> /8 in u32 units... (18432B = 4608 u32)
        #pragma unroll
        for (int kk = 0; kk < 32; kk += 8) {
            uint32_t afr[2][4];
            #pragma unroll
            for (int mt = 0; mt < 2; mt++) {
                int r = mOff + mt * 16 + grp;
                afr[mt][0] = As[r * TILE_STRIDE + kk + tig];
                afr[mt][1] = As[(r + 8) * TILE_STRIDE + kk + tig];
                afr[mt][2] = As[r * TILE_STRIDE + kk + tig + 4];
                afr[mt][3] = As[(r + 8) * TILE_STRIDE + kk + tig + 4];
            }
            #pragma unroll
            for (int nt = 0; nt < 8; nt++) {
                int n = nOff + nt * 8 + grp;
                uint32_t b0 = Bs[n * TILE_STRIDE + kk + tig];
                uint32_t b1 = Bs[n * TILE_STRIDE + kk + tig + 4];
                mma_tf32(acc[0][nt], afr[0], b0, b1);
                mma_tf32(acc[1][nt], afr[1], b0, b1);
            }
        }
        __syncthreads();     // compute done before buffer reuse
    }

    // ---------------- epilogue: registers -> d -> sd (smem) ----------------
    float (*sd)[129] = (float (*)[129])(smem + SM_BUF);
    const float* s_sqi = (const float*)(smem + SM_SQI);
    const float* s_sqj = (const float*)(smem + SM_SQJ);
    const int* s_labi = (const int*)(smem + SM_LABI);
    const int* s_labj = (const int*)(smem + SM_LABJ);

    #pragma unroll
    for (int mt = 0; mt < 2; mt++) {
        int r0 = mOff + mt * 16 + grp;
        float sq0 = s_sqi[r0], sq1 = s_sqi[r0 + 8];
        #pragma unroll
        for (int nt = 0; nt < 8; nt++) {
            int c0 = nOff + nt * 8 + tig * 2;
            float sqa = s_sqj[c0], sqb = s_sqj[c0 + 1];
            const float* a = acc[mt][nt];
            sd[r0][c0]         = sqrtf(fmaxf(sq0 + sqa - 2.f * a[0], 0.f) + 1e-12f);
            sd[r0][c0 + 1]     = sqrtf(fmaxf(sq0 + sqb - 2.f * a[1], 0.f) + 1e-12f);
            sd[r0 + 8][c0]     = sqrtf(fmaxf(sq1 + sqa - 2.f * a[2], 0.f) + 1e-12f);
            sd[r0 + 8][c0 + 1] = sqrtf(fmaxf(sq1 + sqb - 2.f * a[3], 0.f) + 1e-12f);
        }
    }
    __syncthreads();

    // row stats (i-range) and column stats (j-range)
    if (tid < 128) {
        int r = tid, li = s_labi[r];
        float rmax = 0.f, pmax = 0.f;
        #pragma unroll 4
        for (int j = 0; j < 128; j++) {
            float v = sd[r][j];
            rmax = fmaxf(rmax, v);
            if (li == s_labj[j] && (m0 + r) != (n0 + j)) pmax = fmaxf(pmax, v);
        }
        atomicMax((int*)&g_rowmax[m0 + r], __float_as_int(rmax));
        atomicMax((int*)&g_posmax[m0 + r], __float_as_int(pmax));
    } else if (!diag) {
        int q = tid - 128, ljq = s_labj[q];
        float cmax = 0.f, cpmax = 0.f;
        #pragma unroll 4
        for (int r = 0; r < 128; r++) {
            float v = sd[r][q];
            cmax = fmaxf(cmax, v);
            if (s_labi[r] == ljq && (m0 + r) != (n0 + q)) cpmax = fmaxf(cpmax, v);
        }
        atomicMax((int*)&g_rowmax[n0 + q], __float_as_int(cmax));
        atomicMax((int*)&g_posmax[n0 + q], __float_as_int(cpmax));
    }

    // stores: direct block + transposed block
    for (int idx = tid; idx < 4096; idx += 256) {
        int r = idx >> 5, c4 = (idx & 31) * 4;
        float4 v = make_float4(sd[r][c4], sd[r][c4 + 1], sd[r][c4 + 2], sd[r][c4 + 3]);
        *reinterpret_cast<float4*>(&g_dist[(size_t)(m0 + r) * NROW + n0 + c4]) = v;
    }
    if (!diag) {
        for (int idx = tid; idx < 4096; idx += 256) {
            int q = idx >> 5, r4 = (idx & 31) * 4;
            float4 v = make_float4(sd[r4][q], sd[r4 + 1][q], sd[r4 + 2][q], sd[r4 + 3][q]);
            *reinterpret_cast<float4*>(&g_dist[(size_t)(n0 + q) * NROW + m0 + r4]) = v;
        }
    }
}

// ---------------------------------------------------------------------------
// Kernel 2: hardest negative per row.
//   negative_distance[i][j] = dist[i][j] + max_distance[j] * not_negative[i][j]
// ---------------------------------------------------------------------------
__global__ void hneg_kernel(const int* __restrict__ lab) {
    const int i = blockIdx.x;
    const int li = lab[i];
    const float* drow = g_dist + (size_t)i * NROW;
    float mn = 3.4028235e38f;
    for (int j = threadIdx.x; j < NROW; j += blockDim.x) {
        float v = drow[j];
        if (lab[j] == li || j == i) v += g_rowmax[j];
        mn = fminf(mn, v);
    }
    #pragma unroll
    for (int o = 16; o > 0; o >>= 1) mn = fminf(mn, __shfl_xor_sync(0xffffffffu, mn, o));
    __shared__ float ws[8];
    if ((threadIdx.x & 31) == 0) ws[threadIdx.x >> 5] = mn;
    __syncthreads();
    if (threadIdx.x == 0) {
        float m = ws[0];
        #pragma unroll
        for (int w = 1; w < 8; w++) m = fminf(m, ws[w]);
        g_pen[i] = fmaxf(0.5f - m, 0.f);
    }
}

// ---------------------------------------------------------------------------
// Kernel 3: final deterministic reduction -> scalar loss
// ---------------------------------------------------------------------------
__global__ void final_kernel(float* __restrict__ out) {
    float s = 0.f;
    for (int i = threadIdx.x; i < NROW; i += blockDim.x)
        s += g_posmax[i] + g_pen[i];
    #pragma unroll
    for (int o = 16; o > 0; o >>= 1) s += __shfl_xor_sync(0xffffffffu, s, o);
    __shared__ float ws[32];
    if ((threadIdx.x & 31) == 0) ws[threadIdx.x >> 5] = s;
    __syncthreads();
    if (threadIdx.x == 0) {
        float t = 0.f;
        #pragma unroll
        for (int w = 0; w < 32; w++) t += ws[w];
        out[0] = t / (float)NROW;
    }
}

// ---------------------------------------------------------------------------
extern "C" void kernel_launch(void* const* d_in, const int* in_sizes, int n_in,
                              void* d_out, int out_size) {
    const float* X = (const float*)d_in[0];
    const int* lab = (const int*)d_in[1];
    float* out = (float*)d_out;

    cudaFuncSetAttribute(dist_kernel, cudaFuncAttributeMaxDynamicSharedMemorySize, SMEM_TOTAL);

    conv_kernel<<<NROW, 128>>>(X);
    dist_kernel<<<dim3(32, 32), 256, SMEM_TOTAL>>>(lab);
    hneg_kernel<<<NROW, 256>>>(lab);
    final_kernel<<<1, 1024>>>(out);
}